// round 2
// baseline (speedup 1.0000x reference)
#include <cuda_runtime.h>
#include <math.h>

// ContrastiveLoss fused kernel.
// Inputs (metadata order): x [M,D] f32, track_idxs [M] i32, y [n,Q,D] f32.
// Output: scalar f32 loss.
//
// loss = mean_i( -log(num_i / (num_i + den_i)) ) / Q  with
//   num_i = P_i + (G_i - DS_i)/2
//   den_i = (A_i - P_i) + (RT_i - G_i)
// where, with E_xy = exp(x yf^T / T), E_xx = exp(x x^T / T):
//   A_i  = sum of E_xy rows of track i (all cols)
//   P_i  = sum of E_xy over (row track i, col label == i), col label = k % n
//   RT_i = sum of E_xx rows of track i (all cols, ordered, incl diag)
//   G_i  = sum of E_xx over ordered same-track pairs (incl diag)
//   DS_i = sum of diagonal E_xx for track i

#define BM 128
#define BN 128
#define KC 32
#define MAX_M 8192
#define MAX_NQ 4096
#define MAX_D 128

typedef unsigned long long u64;

__device__ float  g_xT[MAX_D * (size_t)MAX_M];   // [D][M]  transposed x
__device__ float  g_yT[MAX_D * (size_t)MAX_NQ];  // [D][nQ] transposed yf
__device__ double g_A[MAX_M];
__device__ double g_P[MAX_M];
__device__ double g_RT[MAX_M];
__device__ double g_G[MAX_M];
__device__ double g_DS[MAX_M];
__device__ int    g_n;

__device__ __forceinline__ u64 pk2(float lo, float hi) {
    u64 r; asm("mov.b64 %0, {%1, %2};" : "=l"(r) : "f"(lo), "f"(hi)); return r;
}
__device__ __forceinline__ void upk2(u64 v, float& lo, float& hi) {
    asm("mov.b64 {%0, %1}, %2;" : "=f"(lo), "=f"(hi) : "l"(v));
}
__device__ __forceinline__ void fma2(u64& c, u64 a, u64 b) {
    asm("fma.rn.f32x2 %0, %1, %2, %0;" : "+l"(c) : "l"(a), "l"(b));
}
__device__ __forceinline__ float ex2f(float x) {
    float r; asm("ex2.approx.f32 %0, %1;" : "=f"(r) : "f"(x)); return r;
}

// ---------------------------------------------------------------------------
__global__ void k_init() {
    int i = blockIdx.x * blockDim.x + threadIdx.x;
    if (i < MAX_M) {
        g_A[i] = 0.0; g_P[i] = 0.0; g_RT[i] = 0.0; g_G[i] = 0.0; g_DS[i] = 0.0;
    }
    if (i == 0) g_n = 0;
}

__global__ void k_max(const int* __restrict__ trk, int M) {
    int i = blockIdx.x * blockDim.x + threadIdx.x;
    if (i < M) atomicMax(&g_n, trk[i] + 1);
}

// Transpose src[rows][D] -> dst[D][rows]
__global__ void k_tr(const float* __restrict__ src, int rows, int D, int toY) {
    float* dst = toY ? g_yT : g_xT;
    int idx = blockIdx.x * blockDim.x + threadIdx.x;
    if (idx < rows * D) {
        int m = idx / D, k = idx % D;
        dst[(size_t)k * rows + m] = src[idx];
    }
}

// ---------------------------------------------------------------------------
// x @ x^T upper-triangle tiles (bR <= bC), fused exp + track reductions.
__global__ void __launch_bounds__(256, 2) k_xx(const int* __restrict__ trk, int M, int D) {
    int bC = blockIdx.x, bR = blockIdx.y;
    if (bR > bC) return;

    __shared__ float As[KC * BM];
    __shared__ float Bs[KC * BN];
    __shared__ int   trS[BM];
    __shared__ int   tcS[BN];
    __shared__ float colsum[BN];

    int tid = threadIdx.x;
    int tx = tid & 15, ty = tid >> 4;

    if (tid < BM) trS[tid] = trk[bR * BM + tid];
    if (tid < BN) { tcS[tid] = trk[bC * BN + tid]; colsum[tid] = 0.f; }

    u64 acc[4][8];
#pragma unroll
    for (int i = 0; i < 4; i++)
#pragma unroll
        for (int j = 0; j < 8; j++) acc[i][j] = 0ull;

    for (int kc = 0; kc < D; kc += KC) {
        __syncthreads();
#pragma unroll
        for (int it = 0; it < 4; it++) {
            int fidx = tid + it * 256;          // 0..1023 float4s
            int k = fidx >> 5;                  // 0..31
            int m4 = (fidx & 31) << 2;          // 0..124
            *reinterpret_cast<float4*>(&As[k * BM + m4]) =
                *reinterpret_cast<const float4*>(&g_xT[(size_t)(kc + k) * M + bR * BM + m4]);
            *reinterpret_cast<float4*>(&Bs[k * BN + m4]) =
                *reinterpret_cast<const float4*>(&g_xT[(size_t)(kc + k) * M + bC * BN + m4]);
        }
        __syncthreads();
#pragma unroll 8
        for (int k = 0; k < KC; k++) {
            float4 a0 = *reinterpret_cast<const float4*>(&As[k * BM + ty * 8]);
            float4 a1 = *reinterpret_cast<const float4*>(&As[k * BM + ty * 8 + 4]);
            float4 b0 = *reinterpret_cast<const float4*>(&Bs[k * BN + tx * 4]);
            float4 b1 = *reinterpret_cast<const float4*>(&Bs[k * BN + 64 + tx * 4]);
            u64 a2[4] = { pk2(a0.x, a0.y), pk2(a0.z, a0.w), pk2(a1.x, a1.y), pk2(a1.z, a1.w) };
            u64 bd[8] = { pk2(b0.x, b0.x), pk2(b0.y, b0.y), pk2(b0.z, b0.z), pk2(b0.w, b0.w),
                          pk2(b1.x, b1.x), pk2(b1.y, b1.y), pk2(b1.z, b1.z), pk2(b1.w, b1.w) };
#pragma unroll
            for (int i = 0; i < 4; i++)
#pragma unroll
                for (int j = 0; j < 8; j++)
                    fma2(acc[i][j], a2[i], bd[j]);
        }
    }

    const float S = 1.4426950408889634f / 0.3f;   // log2(e)/TEMP
    int r0 = ty * 8;
    int cloc[8];
#pragma unroll
    for (int j = 0; j < 8; j++) cloc[j] = (j < 4) ? (tx * 4 + j) : (64 + tx * 4 + j - 4);
    bool diagB = (bR == bC);

    int trI[8], tcJ[8];
#pragma unroll
    for (int i = 0; i < 8; i++) trI[i] = trS[r0 + i];
#pragma unroll
    for (int j = 0; j < 8; j++) tcJ[j] = tcS[cloc[j]];

    float rs[8] = {0}, ss[8] = {0}, cs[8] = {0}, ds[8] = {0};
#pragma unroll
    for (int i = 0; i < 4; i++) {
#pragma unroll
        for (int j = 0; j < 8; j++) {
            float lo, hi; upk2(acc[i][j], lo, hi);
            float e0 = ex2f(lo * S);
            float e1 = ex2f(hi * S);
            rs[2 * i]     += e0;
            rs[2 * i + 1] += e1;
            cs[j]         += e0 + e1;
            if (trI[2 * i]     == tcJ[j]) ss[2 * i]     += e0;
            if (trI[2 * i + 1] == tcJ[j]) ss[2 * i + 1] += e1;
            if (diagB) {
                if (r0 + 2 * i     == cloc[j]) ds[2 * i]     += e0;
                if (r0 + 2 * i + 1 == cloc[j]) ds[2 * i + 1] += e1;
            }
        }
    }

#pragma unroll
    for (int i = 0; i < 8; i++) {
        float v = rs[i], s = ss[i], d = ds[i];
#pragma unroll
        for (int o = 8; o >= 1; o >>= 1) {
            v += __shfl_xor_sync(0xffffffffu, v, o);
            s += __shfl_xor_sync(0xffffffffu, s, o);
            d += __shfl_xor_sync(0xffffffffu, d, o);
        }
        if (tx == 0) {
            atomicAdd(&g_RT[trI[i]], (double)v);
            atomicAdd(&g_G[trI[i]],  (double)(diagB ? s : 2.0f * s));
            if (diagB) atomicAdd(&g_DS[trI[i]], (double)d);
        }
    }

    if (!diagB) {
#pragma unroll
        for (int j = 0; j < 8; j++) atomicAdd(&colsum[cloc[j]], cs[j]);
        __syncthreads();
        if (tid < BN) atomicAdd(&g_RT[tcS[tid]], (double)colsum[tid]);
    }
}

// ---------------------------------------------------------------------------
// x @ yf^T tiles, fused exp + track reductions (A, P).
__global__ void __launch_bounds__(256, 2) k_xy(const int* __restrict__ trk, int M, int nQ, int D) {
    int bC = blockIdx.x, bR = blockIdx.y;

    __shared__ float As[KC * BM];
    __shared__ float Bs[KC * BN];
    __shared__ int   trS[BM];
    __shared__ int   tcS[BN];

    int tid = threadIdx.x;
    int tx = tid & 15, ty = tid >> 4;
    int n = g_n;

    if (tid < BM) trS[tid] = trk[bR * BM + tid];
    if (tid < BN) tcS[tid] = (bC * BN + tid) % n;   // y column label = k % n

    u64 acc[4][8];
#pragma unroll
    for (int i = 0; i < 4; i++)
#pragma unroll
        for (int j = 0; j < 8; j++) acc[i][j] = 0ull;

    for (int kc = 0; kc < D; kc += KC) {
        __syncthreads();
#pragma unroll
        for (int it = 0; it < 4; it++) {
            int fidx = tid + it * 256;
            int k = fidx >> 5;
            int m4 = (fidx & 31) << 2;
            *reinterpret_cast<float4*>(&As[k * BM + m4]) =
                *reinterpret_cast<const float4*>(&g_xT[(size_t)(kc + k) * M + bR * BM + m4]);
            *reinterpret_cast<float4*>(&Bs[k * BN + m4]) =
                *reinterpret_cast<const float4*>(&g_yT[(size_t)(kc + k) * nQ + bC * BN + m4]);
        }
        __syncthreads();
#pragma unroll 8
        for (int k = 0; k < KC; k++) {
            float4 a0 = *reinterpret_cast<const float4*>(&As[k * BM + ty * 8]);
            float4 a1 = *reinterpret_cast<const float4*>(&As[k * BM + ty * 8 + 4]);
            float4 b0 = *reinterpret_cast<const float4*>(&Bs[k * BN + tx * 4]);
            float4 b1 = *reinterpret_cast<const float4*>(&Bs[k * BN + 64 + tx * 4]);
            u64 a2[4] = { pk2(a0.x, a0.y), pk2(a0.z, a0.w), pk2(a1.x, a1.y), pk2(a1.z, a1.w) };
            u64 bd[8] = { pk2(b0.x, b0.x), pk2(b0.y, b0.y), pk2(b0.z, b0.z), pk2(b0.w, b0.w),
                          pk2(b1.x, b1.x), pk2(b1.y, b1.y), pk2(b1.z, b1.z), pk2(b1.w, b1.w) };
#pragma unroll
            for (int i = 0; i < 4; i++)
#pragma unroll
                for (int j = 0; j < 8; j++)
                    fma2(acc[i][j], a2[i], bd[j]);
        }
    }

    const float S = 1.4426950408889634f / 0.3f;
    int r0 = ty * 8;
    int cloc[8];
#pragma unroll
    for (int j = 0; j < 8; j++) cloc[j] = (j < 4) ? (tx * 4 + j) : (64 + tx * 4 + j - 4);

    int trI[8], tcJ[8];
#pragma unroll
    for (int i = 0; i < 8; i++) trI[i] = trS[r0 + i];
#pragma unroll
    for (int j = 0; j < 8; j++) tcJ[j] = tcS[cloc[j]];

    float rs[8] = {0}, ss[8] = {0};
#pragma unroll
    for (int i = 0; i < 4; i++) {
#pragma unroll
        for (int j = 0; j < 8; j++) {
            float lo, hi; upk2(acc[i][j], lo, hi);
            float e0 = ex2f(lo * S);
            float e1 = ex2f(hi * S);
            rs[2 * i]     += e0;
            rs[2 * i + 1] += e1;
            if (trI[2 * i]     == tcJ[j]) ss[2 * i]     += e0;
            if (trI[2 * i + 1] == tcJ[j]) ss[2 * i + 1] += e1;
        }
    }

#pragma unroll
    for (int i = 0; i < 8; i++) {
        float v = rs[i], s = ss[i];
#pragma unroll
        for (int o = 8; o >= 1; o >>= 1) {
            v += __shfl_xor_sync(0xffffffffu, v, o);
            s += __shfl_xor_sync(0xffffffffu, s, o);
        }
        if (tx == 0) {
            atomicAdd(&g_A[trI[i]], (double)v);
            atomicAdd(&g_P[trI[i]], (double)s);
        }
    }
}

// ---------------------------------------------------------------------------
__global__ void k_loss(float* out, int nQ) {
    __shared__ double warpsum[16];
    int n = g_n;
    int Q = nQ / n;
    double local = 0.0;
    for (int i = threadIdx.x; i < n; i += blockDim.x) {
        double num = g_P[i] + 0.5 * (g_G[i] - g_DS[i]);
        double den = (g_A[i] - g_P[i]) + (g_RT[i] - g_G[i]);
        local += log((num + den) / num);    // = -log(num/(num+den))
    }
#pragma unroll
    for (int o = 16; o >= 1; o >>= 1)
        local += __shfl_xor_sync(0xffffffffu, local, o);
    int lane = threadIdx.x & 31, w = threadIdx.x >> 5;
    if (lane == 0) warpsum[w] = local;
    __syncthreads();
    if (threadIdx.x == 0) {
        double t = 0.0;
        int nw = blockDim.x >> 5;
        for (int i = 0; i < nw; i++) t += warpsum[i];
        out[0] = (float)(t / (double)n / (double)Q);
    }
}

// ---------------------------------------------------------------------------
extern "C" void kernel_launch(void* const* d_in, const int* in_sizes, int n_in,
                              void* d_out, int out_size) {
    const float* x   = (const float*)d_in[0];
    const int*   trk = (const int*)d_in[1];
    const float* y   = (const float*)d_in[2];
    float* out = (float*)d_out;

    int M  = in_sizes[1];
    int D  = in_sizes[0] / M;
    int nQ = in_sizes[2] / D;

    k_init<<<(MAX_M + 255) / 256, 256>>>();
    k_max<<<(M + 255) / 256, 256>>>(trk, M);
    k_tr<<<(M * D + 255) / 256, 256>>>(x, M, D, 0);
    k_tr<<<(nQ * D + 255) / 256, 256>>>(y, nQ, D, 1);

    dim3 gxx(M / BN, M / BM);
    k_xx<<<gxx, 256>>>(trk, M, D);

    dim3 gxy(nQ / BN, M / BM);
    k_xy<<<gxy, 256>>>(trk, M, nQ, D);

    k_loss<<<1, 512>>>(out, nQ);
}

// round 4
// speedup vs baseline: 2.4436x; 2.4436x over previous
#include <cuda_runtime.h>
#include <cuda_bf16.h>
#include <math.h>
#include <stdint.h>

// ContrastiveLoss fused via warp-level bf16 mma.sync (compute_100-safe; no tcgen05).
// Inputs: x [M,D] f32, track_idxs [M] i32, y [n,Q,D] f32. Output: scalar f32.
//
// C = exp(x @ [x | yf]^T / T) reduced on the fly into per-track sums:
//   xx cols: RT (row sums), G (same-track incl diag), DS (diag)
//   xy cols: A (row sums), P (pos-label sums)
// loss = mean_i -log(num/(num+den)) / Q,  num = P + (G-DS)/2,
// den = (A-P) + (RT-G)

#define MAX_M  8192
#define MAX_NQ 4096
#define DK     128
#define TILE   128
#define ASTR   136            // padded row stride in bf16 (272 B)

// smem layout (bytes)
#define SM_A     0
#define SM_B     34816
#define SM_TR    69632
#define SM_TC    70144
#define SM_RRS   70656
#define SM_RSS   71168
#define SM_TOTAL 71680

__device__ __nv_bfloat16 g_xb[(size_t)MAX_M * DK];
__device__ __nv_bfloat16 g_yb[(size_t)MAX_NQ * DK];
__device__ double g_A[MAX_M];
__device__ double g_P[MAX_M];
__device__ double g_RT[MAX_M];
__device__ double g_G[MAX_M];
__device__ double g_DS[MAX_M];
__device__ int    g_n;

__device__ __forceinline__ uint32_t smem_u32(const void* p) {
    uint32_t a;
    asm("{ .reg .u64 t; cvta.to.shared.u64 t, %1; cvt.u32.u64 %0, t; }" : "=r"(a) : "l"(p));
    return a;
}
__device__ __forceinline__ float ex2f(float x) {
    float r; asm("ex2.approx.f32 %0, %1;" : "=f"(r) : "f"(x)); return r;
}
__device__ __forceinline__ void ldmx4(uint32_t* r, uint32_t addr) {
    asm volatile("ldmatrix.sync.aligned.m8n8.x4.shared.b16 {%0,%1,%2,%3}, [%4];"
                 : "=r"(r[0]), "=r"(r[1]), "=r"(r[2]), "=r"(r[3]) : "r"(addr));
}
__device__ __forceinline__ void mma16816(float* d, const uint32_t* a, uint32_t b0, uint32_t b1) {
    asm volatile("mma.sync.aligned.m16n8k16.row.col.f32.bf16.bf16.f32 "
                 "{%0,%1,%2,%3}, {%4,%5,%6,%7}, {%8,%9}, {%0,%1,%2,%3};"
                 : "+f"(d[0]), "+f"(d[1]), "+f"(d[2]), "+f"(d[3])
                 : "r"(a[0]), "r"(a[1]), "r"(a[2]), "r"(a[3]), "r"(b0), "r"(b1));
}

// ---------------------------------------------------------------------------
__global__ void k_init() {
    int i = blockIdx.x * blockDim.x + threadIdx.x;
    if (i < MAX_M) { g_A[i] = 0; g_P[i] = 0; g_RT[i] = 0; g_G[i] = 0; g_DS[i] = 0; }
    if (i == 0) g_n = 0;
}

__global__ void k_max(const int* __restrict__ trk, int M) {
    int i = blockIdx.x * blockDim.x + threadIdx.x;
    if (i < M) atomicMax(&g_n, trk[i] + 1);
}

__global__ void k_cvt(const float* __restrict__ src, int nelem, int toY) {
    __nv_bfloat16* dst = toY ? g_yb : g_xb;
    int i = (blockIdx.x * blockDim.x + threadIdx.x) * 4;
    if (i < nelem) {
        float4 v = *reinterpret_cast<const float4*>(src + i);
        *reinterpret_cast<__nv_bfloat162*>(dst + i)     = __floats2bfloat162_rn(v.x, v.y);
        *reinterpret_cast<__nv_bfloat162*>(dst + i + 2) = __floats2bfloat162_rn(v.z, v.w);
    }
}

// ---------------------------------------------------------------------------
__global__ void __launch_bounds__(256)
k_gemm(const int* __restrict__ trk, int M, int nQ) {
    extern __shared__ char smem[];
    uint32_t sb = smem_u32(smem);
    int tid = threadIdx.x;
    int w = tid >> 5, lane = tid & 31;
    int bC = blockIdx.x, bR = blockIdx.y;
    int n = g_n;

    bool isXX = (bC * TILE < M);
    int gcol0 = isXX ? bC * TILE : 0;          // local-global col base for xx diag test
    int grow0 = bR * TILE;

    int* trS = (int*)(smem + SM_TR);
    int* tcS = (int*)(smem + SM_TC);
    float* rowRS = (float*)(smem + SM_RRS);
    float* rowSS = (float*)(smem + SM_RSS);

    if (tid < 128) {
        trS[tid] = trk[grow0 + tid];
        int gc = bC * TILE + tid;
        tcS[tid] = isXX ? trk[gc] : (gc - M) % n;
        rowRS[tid] = 0.f;
        rowSS[tid] = 0.f;
    }

    // ---- load tiles (row-major, padded stride) ----
    const __nv_bfloat16* asrc = g_xb + (size_t)bR * TILE * DK;
    const __nv_bfloat16* bsrc = isXX ? (g_xb + (size_t)bC * TILE * DK)
                                     : (g_yb + ((size_t)bC * TILE - M) * DK);
#pragma unroll
    for (int it = 0; it < 8; it++) {
        int c = tid + it * 256;               // 0..2047 uint4s
        int row = c >> 4;
        int col8 = (c & 15) << 3;             // bf16 index
        uint4 va = *reinterpret_cast<const uint4*>(asrc + (size_t)row * DK + col8);
        uint4 vb = *reinterpret_cast<const uint4*>(bsrc + (size_t)row * DK + col8);
        *reinterpret_cast<uint4*>(smem + SM_A + (row * ASTR + col8) * 2) = va;
        *reinterpret_cast<uint4*>(smem + SM_B + (row * ASTR + col8) * 2) = vb;
    }
    __syncthreads();

    // ---- warp-tile mma: 64(M) x 32(N) per warp ----
    int m0 = (w >> 2) * 64;
    int n0 = (w & 3) * 32;
    int lrow = lane & 15;
    int lk = (lane >> 4) * 8;

    uint32_t aAddr[4], bAddr[2];
#pragma unroll
    for (int mi = 0; mi < 4; mi++)
        aAddr[mi] = sb + SM_A + ((m0 + mi * 16 + lrow) * ASTR + lk) * 2;
#pragma unroll
    for (int g = 0; g < 2; g++)
        bAddr[g] = sb + SM_B + ((n0 + g * 16 + lrow) * ASTR + lk) * 2;

    float acc[4][4][4];
#pragma unroll
    for (int mi = 0; mi < 4; mi++)
#pragma unroll
        for (int ni = 0; ni < 4; ni++)
#pragma unroll
            for (int e = 0; e < 4; e++) acc[mi][ni][e] = 0.f;

#pragma unroll
    for (int ks = 0; ks < 8; ks++) {
        uint32_t a[4][4], b[2][4];
#pragma unroll
        for (int mi = 0; mi < 4; mi++) ldmx4(a[mi], aAddr[mi] + ks * 32);
#pragma unroll
        for (int g = 0; g < 2; g++) ldmx4(b[g], bAddr[g] + ks * 32);
#pragma unroll
        for (int mi = 0; mi < 4; mi++) {
            mma16816(acc[mi][0], a[mi], b[0][0], b[0][2]);
            mma16816(acc[mi][1], a[mi], b[0][1], b[0][3]);
            mma16816(acc[mi][2], a[mi], b[1][0], b[1][2]);
            mma16816(acc[mi][3], a[mi], b[1][1], b[1][3]);
        }
    }

    // ---- fused epilogue: exp + row reductions ----
    const float S = 1.4426950408889634f / 0.3f;   // log2(e)/TEMP
    int q = lane >> 2, t4 = lane & 3;

#pragma unroll
    for (int mi = 0; mi < 4; mi++) {
#pragma unroll
        for (int h = 0; h < 2; h++) {
            int rloc = m0 + mi * 16 + q + h * 8;
            int tr = trS[rloc];
            int grow = grow0 + rloc;
            float r_s = 0.f, s_s = 0.f;
#pragma unroll
            for (int ni = 0; ni < 4; ni++) {
#pragma unroll
                for (int p = 0; p < 2; p++) {
                    float v = acc[mi][ni][h * 2 + p];
                    float e = ex2f(v * S);
                    r_s += e;
                    int cloc = n0 + ni * 8 + t4 * 2 + p;
                    if (tcS[cloc] == tr) s_s += e;
                    if (isXX && (gcol0 + cloc == grow))
                        atomicAdd(&g_DS[tr], (double)e);
                }
            }
            r_s += __shfl_xor_sync(0xffffffffu, r_s, 1);
            r_s += __shfl_xor_sync(0xffffffffu, r_s, 2);
            s_s += __shfl_xor_sync(0xffffffffu, s_s, 1);
            s_s += __shfl_xor_sync(0xffffffffu, s_s, 2);
            if (t4 == 0) {
                atomicAdd(&rowRS[rloc], r_s);
                atomicAdd(&rowSS[rloc], s_s);
            }
        }
    }
    __syncthreads();

    if (tid < 128) {
        int t = trS[tid];
        double* RS = isXX ? g_RT : g_A;
        double* SS = isXX ? g_G : g_P;
        atomicAdd(&RS[t], (double)rowRS[tid]);
        atomicAdd(&SS[t], (double)rowSS[tid]);
    }
}

// ---------------------------------------------------------------------------
__global__ void k_loss(float* out, int nQ) {
    __shared__ double warpsum[16];
    int n = g_n;
    int Q = nQ / n;
    double local = 0.0;
    for (int i = threadIdx.x; i < n; i += blockDim.x) {
        double num = g_P[i] + 0.5 * (g_G[i] - g_DS[i]);
        double den = (g_A[i] - g_P[i]) + (g_RT[i] - g_G[i]);
        local += log((num + den) / num);
    }
#pragma unroll
    for (int o = 16; o >= 1; o >>= 1)
        local += __shfl_xor_sync(0xffffffffu, local, o);
    int lane = threadIdx.x & 31, wi = threadIdx.x >> 5;
    if (lane == 0) warpsum[wi] = local;
    __syncthreads();
    if (threadIdx.x == 0) {
        double t = 0.0;
        for (int i = 0; i < (int)(blockDim.x >> 5); i++) t += warpsum[i];
        out[0] = (float)(t / (double)n / (double)Q);
    }
}

// ---------------------------------------------------------------------------
extern "C" void kernel_launch(void* const* d_in, const int* in_sizes, int n_in,
                              void* d_out, int out_size) {
    const float* x   = (const float*)d_in[0];
    const int*   trk = (const int*)d_in[1];
    const float* y   = (const float*)d_in[2];
    float* out = (float*)d_out;

    int M  = in_sizes[1];
    int D  = in_sizes[0] / M;
    int nQ = in_sizes[2] / D;

    cudaFuncSetAttribute(k_gemm, cudaFuncAttributeMaxDynamicSharedMemorySize, SM_TOTAL);

    k_init<<<(MAX_M + 255) / 256, 256>>>();
    k_max<<<(M + 255) / 256, 256>>>(trk, M);
    k_cvt<<<(M * D / 4 + 255) / 256, 256>>>(x, M * D, 0);
    k_cvt<<<(nQ * D / 4 + 255) / 256, 256>>>(y, nQ * D, 1);

    dim3 grid((M + nQ) / TILE, M / TILE);
    k_gemm<<<grid, 256, SM_TOTAL>>>(trk, M, nQ);

    k_loss<<<1, 512>>>(out, nQ);
}

// round 5
// speedup vs baseline: 2.9690x; 1.2150x over previous
#include <cuda_runtime.h>
#include <cuda_bf16.h>
#include <math.h>
#include <stdint.h>

// ContrastiveLoss fused via warp-level bf16 mma.sync, xx-symmetric (triangle).
// Inputs: x [M,D] f32, track_idxs [M] i32, y [n,Q,D] f32. Output: scalar f32.
//
// C = exp(x @ [x | yf]^T / T) reduced on the fly into per-track sums:
//   xx: RT (row sums), G (ordered same-track sums incl diag), DS (diag)
//   xy: A (row sums), P (pos-label sums)
// xx computed on upper-triangle tiles only; off-diagonal tiles contribute
// rows (RT, 2*G) and, via symmetry, columns (RT).
// loss = mean_i -log(num/(num+den)) / Q, num = P + (G-DS)/2,
// den = (A-P) + (RT-G)

#define MAX_M  8192
#define MAX_NQ 4096
#define DK     128
#define TILE   128
#define ASTR   136            // padded row stride in bf16 (272 B)

// smem layout (bytes)
#define SM_A     0
#define SM_B     34816
#define SM_TR    69632
#define SM_TC    70144
#define SM_RRS   70656
#define SM_RSS   71168
#define SM_CCS   71680
#define SM_TOTAL 72192

__device__ __nv_bfloat16 g_xb[(size_t)MAX_M * DK];
__device__ __nv_bfloat16 g_yb[(size_t)MAX_NQ * DK];
__device__ double g_A[MAX_M];
__device__ double g_P[MAX_M];
__device__ double g_RT[MAX_M];
__device__ double g_G[MAX_M];
__device__ double g_DS[MAX_M];
__device__ int    g_n;

__device__ __forceinline__ uint32_t smem_u32(const void* p) {
    uint32_t a;
    asm("{ .reg .u64 t; cvta.to.shared.u64 t, %1; cvt.u32.u64 %0, t; }" : "=r"(a) : "l"(p));
    return a;
}
__device__ __forceinline__ float ex2f(float x) {
    float r; asm("ex2.approx.f32 %0, %1;" : "=f"(r) : "f"(x)); return r;
}
__device__ __forceinline__ void ldmx4(uint32_t* r, uint32_t addr) {
    asm volatile("ldmatrix.sync.aligned.m8n8.x4.shared.b16 {%0,%1,%2,%3}, [%4];"
                 : "=r"(r[0]), "=r"(r[1]), "=r"(r[2]), "=r"(r[3]) : "r"(addr));
}
__device__ __forceinline__ void mma16816(float* d, const uint32_t* a, uint32_t b0, uint32_t b1) {
    asm volatile("mma.sync.aligned.m16n8k16.row.col.f32.bf16.bf16.f32 "
                 "{%0,%1,%2,%3}, {%4,%5,%6,%7}, {%8,%9}, {%0,%1,%2,%3};"
                 : "+f"(d[0]), "+f"(d[1]), "+f"(d[2]), "+f"(d[3])
                 : "r"(a[0]), "r"(a[1]), "r"(a[2]), "r"(a[3]), "r"(b0), "r"(b1));
}

// ---------------------------------------------------------------------------
__global__ void k_zero() {
    int i = blockIdx.x * blockDim.x + threadIdx.x;
    if (i < MAX_M) { g_A[i] = 0; g_P[i] = 0; g_RT[i] = 0; g_G[i] = 0; g_DS[i] = 0; }
    if (i == 0) g_n = 0;
}

// fused: f32->bf16 conversion of x and y, plus track max
__global__ void k_prep(const float* __restrict__ x, const float* __restrict__ y,
                       const int* __restrict__ trk, int M, int nQ) {
    int t = blockIdx.x * blockDim.x + threadIdx.x;
    int nx4 = M * DK / 4;
    int ny4 = nQ * DK / 4;
    if (t < nx4) {
        float4 v = *reinterpret_cast<const float4*>(x + t * 4);
        *reinterpret_cast<__nv_bfloat162*>(g_xb + t * 4)     = __floats2bfloat162_rn(v.x, v.y);
        *reinterpret_cast<__nv_bfloat162*>(g_xb + t * 4 + 2) = __floats2bfloat162_rn(v.z, v.w);
    } else if (t < nx4 + ny4) {
        int i = t - nx4;
        float4 v = *reinterpret_cast<const float4*>(y + i * 4);
        *reinterpret_cast<__nv_bfloat162*>(g_yb + i * 4)     = __floats2bfloat162_rn(v.x, v.y);
        *reinterpret_cast<__nv_bfloat162*>(g_yb + i * 4 + 2) = __floats2bfloat162_rn(v.z, v.w);
    }
    if (t < M) atomicMax(&g_n, trk[t] + 1);
}

// ---------------------------------------------------------------------------
__global__ void __launch_bounds__(256)
k_gemm(const int* __restrict__ trk, int M, int nQ) {
    int bC = blockIdx.x, bR = blockIdx.y;
    int nXX = M / TILE;
    bool isXX = (bC < nXX);
    if (isXX && bR > bC) return;               // triangle
    bool offDiag = isXX && (bR < bC);
    bool hasDiag = isXX && (bR == bC);

    extern __shared__ char smem[];
    uint32_t sb = smem_u32(smem);
    int tid = threadIdx.x;
    int w = tid >> 5, lane = tid & 31;
    int n = g_n;

    int gcol0 = bC * TILE;
    int grow0 = bR * TILE;

    int* trS = (int*)(smem + SM_TR);
    int* tcS = (int*)(smem + SM_TC);
    float* rowRS = (float*)(smem + SM_RRS);
    float* rowSS = (float*)(smem + SM_RSS);
    float* colCS = (float*)(smem + SM_CCS);

    if (tid < 128) {
        trS[tid] = trk[grow0 + tid];
        int gc = gcol0 + tid;
        tcS[tid] = isXX ? trk[gc] : (gc - M) % n;
        rowRS[tid] = 0.f;
        rowSS[tid] = 0.f;
        colCS[tid] = 0.f;
    }

    // ---- load tiles ----
    const __nv_bfloat16* asrc = g_xb + (size_t)bR * TILE * DK;
    const __nv_bfloat16* bsrc = isXX ? (g_xb + (size_t)bC * TILE * DK)
                                     : (g_yb + ((size_t)gcol0 - M) * DK);
#pragma unroll
    for (int it = 0; it < 8; it++) {
        int c = tid + it * 256;
        int row = c >> 4;
        int col8 = (c & 15) << 3;
        uint4 va = *reinterpret_cast<const uint4*>(asrc + (size_t)row * DK + col8);
        uint4 vb = *reinterpret_cast<const uint4*>(bsrc + (size_t)row * DK + col8);
        *reinterpret_cast<uint4*>(smem + SM_A + (row * ASTR + col8) * 2) = va;
        *reinterpret_cast<uint4*>(smem + SM_B + (row * ASTR + col8) * 2) = vb;
    }
    __syncthreads();

    // ---- warp-tile mma: 64(M) x 32(N) per warp ----
    int m0 = (w >> 2) * 64;
    int n0 = (w & 3) * 32;
    int lrow = lane & 15;
    int lk = (lane >> 4) * 8;

    uint32_t aAddr[4], bAddr[2];
#pragma unroll
    for (int mi = 0; mi < 4; mi++)
        aAddr[mi] = sb + SM_A + ((m0 + mi * 16 + lrow) * ASTR + lk) * 2;
#pragma unroll
    for (int g = 0; g < 2; g++)
        bAddr[g] = sb + SM_B + ((n0 + g * 16 + lrow) * ASTR + lk) * 2;

    float acc[4][4][4];
#pragma unroll
    for (int mi = 0; mi < 4; mi++)
#pragma unroll
        for (int ni = 0; ni < 4; ni++)
#pragma unroll
            for (int e = 0; e < 4; e++) acc[mi][ni][e] = 0.f;

#pragma unroll
    for (int ks = 0; ks < 8; ks++) {
        uint32_t a[4][4], b[2][4];
#pragma unroll
        for (int mi = 0; mi < 4; mi++) ldmx4(a[mi], aAddr[mi] + ks * 32);
#pragma unroll
        for (int g = 0; g < 2; g++) ldmx4(b[g], bAddr[g] + ks * 32);
#pragma unroll
        for (int mi = 0; mi < 4; mi++) {
            mma16816(acc[mi][0], a[mi], b[0][0], b[0][2]);
            mma16816(acc[mi][1], a[mi], b[0][1], b[0][3]);
            mma16816(acc[mi][2], a[mi], b[1][0], b[1][2]);
            mma16816(acc[mi][3], a[mi], b[1][1], b[1][3]);
        }
    }

    // ---- fused epilogue ----
    const float S = 1.4426950408889634f / 0.3f;   // log2(e)/TEMP
    int q = lane >> 2, t4 = lane & 3;
    float cs[4][2] = {{0.f, 0.f}, {0.f, 0.f}, {0.f, 0.f}, {0.f, 0.f}};

#pragma unroll
    for (int mi = 0; mi < 4; mi++) {
#pragma unroll
        for (int h = 0; h < 2; h++) {
            int rloc = m0 + mi * 16 + q + h * 8;
            int tr = trS[rloc];
            int grow = grow0 + rloc;
            float r_s = 0.f, s_s = 0.f;
#pragma unroll
            for (int ni = 0; ni < 4; ni++) {
#pragma unroll
                for (int p = 0; p < 2; p++) {
                    float v = acc[mi][ni][h * 2 + p];
                    float e = ex2f(v * S);
                    r_s += e;
                    int cloc = n0 + ni * 8 + t4 * 2 + p;
                    if (tcS[cloc] == tr) s_s += e;
                    if (hasDiag && (gcol0 + cloc == grow))
                        atomicAdd(&g_DS[tr], (double)e);
                    if (offDiag) cs[ni][p] += e;
                }
            }
            r_s += __shfl_xor_sync(0xffffffffu, r_s, 1);
            r_s += __shfl_xor_sync(0xffffffffu, r_s, 2);
            s_s += __shfl_xor_sync(0xffffffffu, s_s, 1);
            s_s += __shfl_xor_sync(0xffffffffu, s_s, 2);
            if (t4 == 0) {
                atomicAdd(&rowRS[rloc], r_s);
                atomicAdd(&rowSS[rloc], s_s);
            }
        }
    }

    if (offDiag) {
        // reduce column partials over the quad axis (q = lane>>2)
#pragma unroll
        for (int ni = 0; ni < 4; ni++) {
#pragma unroll
            for (int p = 0; p < 2; p++) {
                float v = cs[ni][p];
                v += __shfl_xor_sync(0xffffffffu, v, 4);
                v += __shfl_xor_sync(0xffffffffu, v, 8);
                v += __shfl_xor_sync(0xffffffffu, v, 16);
                if (q == 0) {
                    int cloc = n0 + ni * 8 + t4 * 2 + p;
                    atomicAdd(&colCS[cloc], v);
                }
            }
        }
    }
    __syncthreads();

    if (tid < 128) {
        int t = trS[tid];
        if (isXX) {
            atomicAdd(&g_RT[t], (double)rowRS[tid]);
            atomicAdd(&g_G[t], (double)((offDiag ? 2.0f : 1.0f) * rowSS[tid]));
            if (offDiag)
                atomicAdd(&g_RT[tcS[tid]], (double)colCS[tid]);   // symmetric cols
        } else {
            atomicAdd(&g_A[t], (double)rowRS[tid]);
            atomicAdd(&g_P[t], (double)rowSS[tid]);
        }
    }
}

// ---------------------------------------------------------------------------
__global__ void k_loss(float* out, int nQ) {
    __shared__ double warpsum[16];
    int n = g_n;
    int Q = nQ / n;
    double local = 0.0;
    for (int i = threadIdx.x; i < n; i += blockDim.x) {
        double num = g_P[i] + 0.5 * (g_G[i] - g_DS[i]);
        double den = (g_A[i] - g_P[i]) + (g_RT[i] - g_G[i]);
        local += log((num + den) / num);
    }
#pragma unroll
    for (int o = 16; o >= 1; o >>= 1)
        local += __shfl_xor_sync(0xffffffffu, local, o);
    int lane = threadIdx.x & 31, wi = threadIdx.x >> 5;
    if (lane == 0) warpsum[wi] = local;
    __syncthreads();
    if (threadIdx.x == 0) {
        double t = 0.0;
        for (int i = 0; i < (int)(blockDim.x >> 5); i++) t += warpsum[i];
        out[0] = (float)(t / (double)n / (double)Q);
    }
}

// ---------------------------------------------------------------------------
extern "C" void kernel_launch(void* const* d_in, const int* in_sizes, int n_in,
                              void* d_out, int out_size) {
    const float* x   = (const float*)d_in[0];
    const int*   trk = (const int*)d_in[1];
    const float* y   = (const float*)d_in[2];
    float* out = (float*)d_out;

    int M  = in_sizes[1];
    int D  = in_sizes[0] / M;
    int nQ = in_sizes[2] / D;

    cudaFuncSetAttribute(k_gemm, cudaFuncAttributeMaxDynamicSharedMemorySize, SM_TOTAL);

    k_zero<<<(MAX_M + 255) / 256, 256>>>();
    int prepThreads = (M * D + nQ * D) / 4;
    k_prep<<<(prepThreads + 255) / 256, 256>>>(x, y, trk, M, nQ);

    dim3 grid((M + nQ) / TILE, M / TILE);
    k_gemm<<<grid, 256, SM_TOTAL>>>(trk, M, nQ);

    k_loss<<<1, 512>>>(out, nQ);
}

// round 6
// speedup vs baseline: 3.2699x; 1.1013x over previous
#include <cuda_runtime.h>
#include <cuda_bf16.h>
#include <math.h>
#include <stdint.h>

// ContrastiveLoss fused via warp-level bf16 mma.sync, xx-symmetric triangle,
// persistent CTAs with cp.async prefetch (loads hidden under epilogue).
// Inputs: x [M,D] f32, track_idxs [M] i32, y [n,Q,D] f32. Output: scalar f32.

#define MAX_M  8192
#define DK     128
#define TILE   128
#define ASTR   136            // padded row stride in bf16 (272 B)
#define NPCTA  296            // persistent grid (2 per SM x 148 SMs)

// smem layout (bytes)
#define SM_A     0
#define SM_B     34816
#define SM_TR    69632        // 2 x 512 (double-buffered row labels)
#define SM_TC    70656        // 2 x 512 (double-buffered col labels)
#define SM_RRS   71680
#define SM_RSS   72192
#define SM_CCS   72704
#define SM_TOTAL 73216

__device__ __nv_bfloat16 g_xb[(size_t)MAX_M * DK];
__device__ __nv_bfloat16 g_yb[(size_t)MAX_M * DK / 2];
__device__ double g_A[MAX_M];
__device__ double g_P[MAX_M];
__device__ double g_RT[MAX_M];
__device__ double g_G[MAX_M];
__device__ double g_DS[MAX_M];
__device__ int    g_n;

__device__ __forceinline__ uint32_t smem_u32(const void* p) {
    uint32_t a;
    asm("{ .reg .u64 t; cvta.to.shared.u64 t, %1; cvt.u32.u64 %0, t; }" : "=r"(a) : "l"(p));
    return a;
}
__device__ __forceinline__ float ex2f(float x) {
    float r; asm("ex2.approx.f32 %0, %1;" : "=f"(r) : "f"(x)); return r;
}
__device__ __forceinline__ void ldmx4(uint32_t* r, uint32_t addr) {
    asm volatile("ldmatrix.sync.aligned.m8n8.x4.shared.b16 {%0,%1,%2,%3}, [%4];"
                 : "=r"(r[0]), "=r"(r[1]), "=r"(r[2]), "=r"(r[3]) : "r"(addr));
}
__device__ __forceinline__ void mma16816(float* d, const uint32_t* a, uint32_t b0, uint32_t b1) {
    asm volatile("mma.sync.aligned.m16n8k16.row.col.f32.bf16.bf16.f32 "
                 "{%0,%1,%2,%3}, {%4,%5,%6,%7}, {%8,%9}, {%0,%1,%2,%3};"
                 : "+f"(d[0]), "+f"(d[1]), "+f"(d[2]), "+f"(d[3])
                 : "r"(a[0]), "r"(a[1]), "r"(a[2]), "r"(a[3]), "r"(b0), "r"(b1));
}
__device__ __forceinline__ void cpasync16(uint32_t saddr, const void* gptr) {
    asm volatile("cp.async.cg.shared.global [%0], [%1], 16;"
                 :: "r"(saddr), "l"(gptr));
}

// ---------------------------------------------------------------------------
__global__ void k_zero() {
    int i = blockIdx.x * blockDim.x + threadIdx.x;
    if (i < MAX_M) { g_A[i] = 0; g_P[i] = 0; g_RT[i] = 0; g_G[i] = 0; g_DS[i] = 0; }
    if (i == 0) g_n = 0;
}

__global__ void k_prep(const float* __restrict__ x, const float* __restrict__ y,
                       const int* __restrict__ trk, int M, int nQ) {
    int t = blockIdx.x * blockDim.x + threadIdx.x;
    int nx4 = M * DK / 4;
    int ny4 = nQ * DK / 4;
    if (t < nx4) {
        float4 v = *reinterpret_cast<const float4*>(x + t * 4);
        *reinterpret_cast<__nv_bfloat162*>(g_xb + t * 4)     = __floats2bfloat162_rn(v.x, v.y);
        *reinterpret_cast<__nv_bfloat162*>(g_xb + t * 4 + 2) = __floats2bfloat162_rn(v.z, v.w);
    } else if (t < nx4 + ny4) {
        int i = t - nx4;
        float4 v = *reinterpret_cast<const float4*>(y + i * 4);
        *reinterpret_cast<__nv_bfloat162*>(g_yb + i * 4)     = __floats2bfloat162_rn(v.x, v.y);
        *reinterpret_cast<__nv_bfloat162*>(g_yb + i * 4 + 2) = __floats2bfloat162_rn(v.z, v.w);
    }
    if (t < M) atomicMax(&g_n, trk[t] + 1);
}

// ---------------------------------------------------------------------------
// tile index -> (bR, bC, isXX). xx tiles: upper triangle row-major; then xy.
__device__ __forceinline__ void tile_coords(int t, int nXX, int tri, int nXYc,
                                            int& bR, int& bC, bool& isXX) {
    if (t < tri) {
        isXX = true;
        float disc = (2.f * nXX + 1.f) * (2.f * nXX + 1.f) - 8.f * (float)t;
        int r = (int)((2.f * nXX + 1.f - sqrtf(disc)) * 0.5f);
        if (r < 0) r = 0;
        if (r > nXX - 1) r = nXX - 1;
        while (r + 1 < nXX && t >= (r + 1) * nXX - ((r + 1) * r) / 2) r++;
        while (r > 0 && t < r * nXX - (r * (r - 1)) / 2) r--;
        bR = r;
        bC = r + t - (r * nXX - (r * (r - 1)) / 2);
    } else {
        isXX = false;
        int u = t - tri;
        bR = u / nXYc;
        bC = u - bR * nXYc;       // xy col-tile index (0-based into y)
    }
}

__global__ void __launch_bounds__(256, 2)
k_gemm(const int* __restrict__ trk, int M, int nQ) {
    extern __shared__ char smem[];
    uint32_t sb = smem_u32(smem);
    int tid = threadIdx.x;
    int w = tid >> 5, lane = tid & 31;
    int n = g_n;

    int nXX = M / TILE;
    int tri = nXX * (nXX + 1) / 2;
    int nXYc = nQ / TILE;
    int totTiles = tri + nXX * nXYc;

    int* trS = (int*)(smem + SM_TR);       // [2][128]
    int* tcS = (int*)(smem + SM_TC);       // [2][128]
    float* rowRS = (float*)(smem + SM_RRS);
    float* rowSS = (float*)(smem + SM_RSS);
    float* colCS = (float*)(smem + SM_CCS);

    if (tid < 128) { rowRS[tid] = 0.f; rowSS[tid] = 0.f; colCS[tid] = 0.f; }

    int m0 = (w >> 2) * 64;
    int n0 = (w & 3) * 32;
    int lrow = lane & 15;
    int lk = (lane >> 4) * 8;
    int q = lane >> 2, t4 = lane & 3;
    const float S = 1.4426950408889634f / 0.3f;   // log2(e)/TEMP

    uint32_t aAddr[4], bAddr[2];
#pragma unroll
    for (int mi = 0; mi < 4; mi++)
        aAddr[mi] = sb + SM_A + ((m0 + mi * 16 + lrow) * ASTR + lk) * 2;
#pragma unroll
    for (int g = 0; g < 2; g++)
        bAddr[g] = sb + SM_B + ((n0 + g * 16 + lrow) * ASTR + lk) * 2;

    // ---- prologue: fetch first tile ----
    int t = blockIdx.x;
    int bR = 0, bC = 0; bool isXX = true;
    int cur = 0;
    if (t < totTiles) {
        tile_coords(t, nXX, tri, nXYc, bR, bC, isXX);
        const __nv_bfloat16* asrc = g_xb + (size_t)bR * TILE * DK;
        const __nv_bfloat16* bsrc = isXX ? (g_xb + (size_t)bC * TILE * DK)
                                         : (g_yb + (size_t)bC * TILE * DK);
#pragma unroll
        for (int it = 0; it < 8; it++) {
            int c = tid + it * 256;
            int row = c >> 4;
            int col8 = (c & 15) << 3;
            cpasync16(sb + SM_A + (row * ASTR + col8) * 2, asrc + (size_t)row * DK + col8);
            cpasync16(sb + SM_B + (row * ASTR + col8) * 2, bsrc + (size_t)row * DK + col8);
        }
        if (tid < 128) {
            trS[tid] = trk[bR * TILE + tid];
            tcS[tid] = isXX ? trk[bC * TILE + tid] : (bC * TILE + tid) % n;
        }
    }
    asm volatile("cp.async.commit_group;" ::: "memory");

    for (; t < totTiles; t += gridDim.x) {
        bool offDiag = isXX && (bR < bC);
        bool hasDiag = isXX && (bR == bC);
        int grow0 = bR * TILE;
        int gcol0 = bC * TILE;          // for xx diag test only

        asm volatile("cp.async.wait_group 0;" ::: "memory");
        __syncthreads();

        // ---- MMA ----
        float acc[4][4][4];
#pragma unroll
        for (int mi = 0; mi < 4; mi++)
#pragma unroll
            for (int ni = 0; ni < 4; ni++)
#pragma unroll
                for (int e = 0; e < 4; e++) acc[mi][ni][e] = 0.f;

#pragma unroll
        for (int ks = 0; ks < 8; ks++) {
            uint32_t a[4][4], b[2][4];
#pragma unroll
            for (int mi = 0; mi < 4; mi++) ldmx4(a[mi], aAddr[mi] + ks * 32);
#pragma unroll
            for (int g = 0; g < 2; g++) ldmx4(b[g], bAddr[g] + ks * 32);
#pragma unroll
            for (int mi = 0; mi < 4; mi++) {
                mma16816(acc[mi][0], a[mi], b[0][0], b[0][2]);
                mma16816(acc[mi][1], a[mi], b[0][1], b[0][3]);
                mma16816(acc[mi][2], a[mi], b[1][0], b[1][2]);
                mma16816(acc[mi][3], a[mi], b[1][1], b[1][3]);
            }
        }
        __syncthreads();   // all warps done reading A/B smem

        // ---- prefetch next tile into the (now dead) A/B buffers ----
        int nt = t + gridDim.x;
        int nbR = 0, nbC = 0; bool nisXX = true;
        if (nt < totTiles) {
            tile_coords(nt, nXX, tri, nXYc, nbR, nbC, nisXX);
            const __nv_bfloat16* asrc = g_xb + (size_t)nbR * TILE * DK;
            const __nv_bfloat16* bsrc = nisXX ? (g_xb + (size_t)nbC * TILE * DK)
                                              : (g_yb + (size_t)nbC * TILE * DK);
#pragma unroll
            for (int it = 0; it < 8; it++) {
                int c = tid + it * 256;
                int row = c >> 4;
                int col8 = (c & 15) << 3;
                cpasync16(sb + SM_A + (row * ASTR + col8) * 2, asrc + (size_t)row * DK + col8);
                cpasync16(sb + SM_B + (row * ASTR + col8) * 2, bsrc + (size_t)row * DK + col8);
            }
            int nx = cur ^ 1;
            if (tid < 128) {
                trS[nx * 128 + tid] = trk[nbR * TILE + tid];
                tcS[nx * 128 + tid] = nisXX ? trk[nbC * TILE + tid]
                                            : (nbC * TILE + tid) % n;
            }
        }
        asm volatile("cp.async.commit_group;" ::: "memory");

        // ---- epilogue (overlaps with in-flight cp.async) ----
        const int* trC = trS + cur * 128;
        const int* tcC = tcS + cur * 128;
        int tcJ[8];
#pragma unroll
        for (int j = 0; j < 8; j++) {
            int ni = j >> 1, p = j & 1;
            tcJ[j] = tcC[n0 + ni * 8 + t4 * 2 + p];
        }

        float cs[4][2] = {{0.f, 0.f}, {0.f, 0.f}, {0.f, 0.f}, {0.f, 0.f}};
#pragma unroll
        for (int mi = 0; mi < 4; mi++) {
#pragma unroll
            for (int h = 0; h < 2; h++) {
                int rloc = m0 + mi * 16 + q + h * 8;
                int tr = trC[rloc];
                int grow = grow0 + rloc;
                float r_s = 0.f, s_s = 0.f;
#pragma unroll
                for (int ni = 0; ni < 4; ni++) {
#pragma unroll
                    for (int p = 0; p < 2; p++) {
                        float v = acc[mi][ni][h * 2 + p];
                        float e = ex2f(v * S);
                        r_s += e;
                        if (tcJ[ni * 2 + p] == tr) s_s += e;
                        if (hasDiag && (gcol0 + n0 + ni * 8 + t4 * 2 + p == grow))
                            atomicAdd(&g_DS[tr], (double)e);
                        if (offDiag) cs[ni][p] += e;
                    }
                }
                r_s += __shfl_xor_sync(0xffffffffu, r_s, 1);
                r_s += __shfl_xor_sync(0xffffffffu, r_s, 2);
                s_s += __shfl_xor_sync(0xffffffffu, s_s, 1);
                s_s += __shfl_xor_sync(0xffffffffu, s_s, 2);
                if (t4 == 0) {
                    atomicAdd(&rowRS[rloc], r_s);
                    atomicAdd(&rowSS[rloc], s_s);
                }
            }
        }

        if (offDiag) {
#pragma unroll
            for (int ni = 0; ni < 4; ni++) {
#pragma unroll
                for (int p = 0; p < 2; p++) {
                    float v = cs[ni][p];
                    v += __shfl_xor_sync(0xffffffffu, v, 4);
                    v += __shfl_xor_sync(0xffffffffu, v, 8);
                    v += __shfl_xor_sync(0xffffffffu, v, 16);
                    if (q == 0)
                        atomicAdd(&colCS[n0 + ni * 8 + t4 * 2 + p], v);
                }
            }
        }
        __syncthreads();

        if (tid < 128) {
            int tr = trC[tid];
            if (isXX) {
                atomicAdd(&g_RT[tr], (double)rowRS[tid]);
                atomicAdd(&g_G[tr], (double)((offDiag ? 2.0f : 1.0f) * rowSS[tid]));
                if (offDiag)
                    atomicAdd(&g_RT[tcC[tid]], (double)colCS[tid]);
            } else {
                atomicAdd(&g_A[tr], (double)rowRS[tid]);
                atomicAdd(&g_P[tr], (double)rowSS[tid]);
            }
            rowRS[tid] = 0.f; rowSS[tid] = 0.f; colCS[tid] = 0.f;
        }

        bR = nbR; bC = nbC; isXX = nisXX;
        cur ^= 1;
    }
}

// ---------------------------------------------------------------------------
__global__ void k_loss(float* out, int nQ) {
    __shared__ double warpsum[16];
    int n = g_n;
    int Q = nQ / n;
    double local = 0.0;
    for (int i = threadIdx.x; i < n; i += blockDim.x) {
        double num = g_P[i] + 0.5 * (g_G[i] - g_DS[i]);
        double den = (g_A[i] - g_P[i]) + (g_RT[i] - g_G[i]);
        local += log((num + den) / num);
    }
#pragma unroll
    for (int o = 16; o >= 1; o >>= 1)
        local += __shfl_xor_sync(0xffffffffu, local, o);
    int lane = threadIdx.x & 31, wi = threadIdx.x >> 5;
    if (lane == 0) warpsum[wi] = local;
    __syncthreads();
    if (threadIdx.x == 0) {
        double t = 0.0;
        for (int i = 0; i < (int)(blockDim.x >> 5); i++) t += warpsum[i];
        out[0] = (float)(t / (double)n / (double)Q);
    }
}

// ---------------------------------------------------------------------------
extern "C" void kernel_launch(void* const* d_in, const int* in_sizes, int n_in,
                              void* d_out, int out_size) {
    const float* x   = (const float*)d_in[0];
    const int*   trk = (const int*)d_in[1];
    const float* y   = (const float*)d_in[2];
    float* out = (float*)d_out;

    int M  = in_sizes[1];
    int D  = in_sizes[0] / M;
    int nQ = in_sizes[2] / D;

    cudaFuncSetAttribute(k_gemm, cudaFuncAttributeMaxDynamicSharedMemorySize, SM_TOTAL);

    k_zero<<<(MAX_M + 255) / 256, 256>>>();
    int prepThreads = (M * D + nQ * D) / 4;
    k_prep<<<(prepThreads + 255) / 256, 256>>>(x, y, trk, M, nQ);

    k_gemm<<<NPCTA, 256, SM_TOTAL>>>(trk, M, nQ);

    k_loss<<<1, 512>>>(out, nQ);
}

// round 7
// speedup vs baseline: 3.3451x; 1.0230x over previous
#include <cuda_runtime.h>
#include <cuda_bf16.h>
#include <math.h>
#include <stdint.h>

// ContrastiveLoss fused via warp-level bf16 mma.sync, xx-symmetric triangle,
// persistent CTAs with cp.async prefetch. A-operand prescaled by log2(e)/T so
// the epilogue is a bare ex2.
// Inputs: x [M,D] f32, track_idxs [M] i32, y [n,Q,D] f32. Output: scalar f32.

#define MAX_M  8192
#define DK     128
#define TILE   128
#define ASTR   136            // padded row stride in bf16 (272 B)
#define NPCTA  296            // persistent grid (2 per SM x 148 SMs)

// smem layout (bytes)
#define SM_A     0
#define SM_B     34816
#define SM_TR    69632        // 2 x 512 (double-buffered row labels)
#define SM_TC    70656        // 2 x 512 (double-buffered col labels)
#define SM_RRS   71680
#define SM_RSS   72192
#define SM_CCS   72704
#define SM_TOTAL 73216

__device__ __nv_bfloat16 g_xb[(size_t)MAX_M * DK];        // unscaled x (B operand)
__device__ __nv_bfloat16 g_xs[(size_t)MAX_M * DK];        // x * log2(e)/T (A operand)
__device__ __nv_bfloat16 g_yb[(size_t)MAX_M * DK / 2];    // unscaled y (B operand)
__device__ double g_A[MAX_M];
__device__ double g_P[MAX_M];
__device__ double g_RT[MAX_M];
__device__ double g_G[MAX_M];
__device__ double g_DS[MAX_M];
__device__ int    g_n = 0;    // monotone atomicMax target; idempotent across replays

__device__ __forceinline__ uint32_t smem_u32(const void* p) {
    uint32_t a;
    asm("{ .reg .u64 t; cvta.to.shared.u64 t, %1; cvt.u32.u64 %0, t; }" : "=r"(a) : "l"(p));
    return a;
}
__device__ __forceinline__ float ex2f(float x) {
    float r; asm("ex2.approx.f32 %0, %1;" : "=f"(r) : "f"(x)); return r;
}
__device__ __forceinline__ void ldmx4(uint32_t* r, uint32_t addr) {
    asm volatile("ldmatrix.sync.aligned.m8n8.x4.shared.b16 {%0,%1,%2,%3}, [%4];"
                 : "=r"(r[0]), "=r"(r[1]), "=r"(r[2]), "=r"(r[3]) : "r"(addr));
}
__device__ __forceinline__ void mma16816(float* d, const uint32_t* a, uint32_t b0, uint32_t b1) {
    asm volatile("mma.sync.aligned.m16n8k16.row.col.f32.bf16.bf16.f32 "
                 "{%0,%1,%2,%3}, {%4,%5,%6,%7}, {%8,%9}, {%0,%1,%2,%3};"
                 : "+f"(d[0]), "+f"(d[1]), "+f"(d[2]), "+f"(d[3])
                 : "r"(a[0]), "r"(a[1]), "r"(a[2]), "r"(a[3]), "r"(b0), "r"(b1));
}
__device__ __forceinline__ void cpasync16(uint32_t saddr, const void* gptr) {
    asm volatile("cp.async.cg.shared.global [%0], [%1], 16;"
                 :: "r"(saddr), "l"(gptr));
}

// ---------------------------------------------------------------------------
// fused: zero accumulators, convert x (scaled + unscaled) and y, track max
__global__ void k_prep(const float* __restrict__ x, const float* __restrict__ y,
                       const int* __restrict__ trk, int M, int nQ) {
    const float S = 1.4426950408889634f / 0.3f;   // log2(e)/TEMP
    int t = blockIdx.x * blockDim.x + threadIdx.x;
    int nx4 = M * DK / 4;
    int ny4 = nQ * DK / 4;
    if (t < nx4) {
        float4 v = *reinterpret_cast<const float4*>(x + t * 4);
        *reinterpret_cast<__nv_bfloat162*>(g_xb + t * 4)     = __floats2bfloat162_rn(v.x, v.y);
        *reinterpret_cast<__nv_bfloat162*>(g_xb + t * 4 + 2) = __floats2bfloat162_rn(v.z, v.w);
        *reinterpret_cast<__nv_bfloat162*>(g_xs + t * 4)     = __floats2bfloat162_rn(v.x * S, v.y * S);
        *reinterpret_cast<__nv_bfloat162*>(g_xs + t * 4 + 2) = __floats2bfloat162_rn(v.z * S, v.w * S);
    } else if (t < nx4 + ny4) {
        int i = t - nx4;
        float4 v = *reinterpret_cast<const float4*>(y + i * 4);
        *reinterpret_cast<__nv_bfloat162*>(g_yb + i * 4)     = __floats2bfloat162_rn(v.x, v.y);
        *reinterpret_cast<__nv_bfloat162*>(g_yb + i * 4 + 2) = __floats2bfloat162_rn(v.z, v.w);
    }
    if (t < MAX_M) { g_A[t] = 0; g_P[t] = 0; g_RT[t] = 0; g_G[t] = 0; g_DS[t] = 0; }
    if (t < M) atomicMax(&g_n, trk[t] + 1);
}

// ---------------------------------------------------------------------------
// tile index -> (bR, bC, isXX). xx tiles: upper triangle row-major; then xy.
__device__ __forceinline__ void tile_coords(int t, int nXX, int tri, int nXYc,
                                            int& bR, int& bC, bool& isXX) {
    if (t < tri) {
        isXX = true;
        float disc = (2.f * nXX + 1.f) * (2.f * nXX + 1.f) - 8.f * (float)t;
        int r = (int)((2.f * nXX + 1.f - sqrtf(disc)) * 0.5f);
        if (r < 0) r = 0;
        if (r > nXX - 1) r = nXX - 1;
        while (r + 1 < nXX && t >= (r + 1) * nXX - ((r + 1) * r) / 2) r++;
        while (r > 0 && t < r * nXX - (r * (r - 1)) / 2) r--;
        bR = r;
        bC = r + t - (r * nXX - (r * (r - 1)) / 2);
    } else {
        isXX = false;
        int u = t - tri;
        bR = u / nXYc;
        bC = u - bR * nXYc;
    }
}

__global__ void __launch_bounds__(256, 2)
k_gemm(const int* __restrict__ trk, int M, int nQ) {
    extern __shared__ char smem[];
    uint32_t sb = smem_u32(smem);
    int tid = threadIdx.x;
    int w = tid >> 5, lane = tid & 31;
    int n = g_n;

    int nXX = M / TILE;
    int tri = nXX * (nXX + 1) / 2;
    int nXYc = nQ / TILE;
    int totTiles = tri + nXX * nXYc;

    int* trS = (int*)(smem + SM_TR);
    int* tcS = (int*)(smem + SM_TC);
    float* rowRS = (float*)(smem + SM_RRS);
    float* rowSS = (float*)(smem + SM_RSS);
    float* colCS = (float*)(smem + SM_CCS);

    if (tid < 128) { rowRS[tid] = 0.f; rowSS[tid] = 0.f; colCS[tid] = 0.f; }

    int m0 = (w >> 2) * 64;
    int n0 = (w & 3) * 32;
    int lrow = lane & 15;
    int lk = (lane >> 4) * 8;
    int q = lane >> 2, t4 = lane & 3;

    uint32_t aAddr[4], bAddr[2];
#pragma unroll
    for (int mi = 0; mi < 4; mi++)
        aAddr[mi] = sb + SM_A + ((m0 + mi * 16 + lrow) * ASTR + lk) * 2;
#pragma unroll
    for (int g = 0; g < 2; g++)
        bAddr[g] = sb + SM_B + ((n0 + g * 16 + lrow) * ASTR + lk) * 2;

    // ---- prologue: fetch first tile ----
    int t = blockIdx.x;
    int bR = 0, bC = 0; bool isXX = true;
    int cur = 0;
    if (t < totTiles) {
        tile_coords(t, nXX, tri, nXYc, bR, bC, isXX);
        const __nv_bfloat16* asrc = g_xs + (size_t)bR * TILE * DK;
        const __nv_bfloat16* bsrc = isXX ? (g_xb + (size_t)bC * TILE * DK)
                                         : (g_yb + (size_t)bC * TILE * DK);
#pragma unroll
        for (int it = 0; it < 8; it++) {
            int c = tid + it * 256;
            int row = c >> 4;
            int col8 = (c & 15) << 3;
            cpasync16(sb + SM_A + (row * ASTR + col8) * 2, asrc + (size_t)row * DK + col8);
            cpasync16(sb + SM_B + (row * ASTR + col8) * 2, bsrc + (size_t)row * DK + col8);
        }
        if (tid < 128) {
            trS[tid] = trk[bR * TILE + tid];
            tcS[tid] = isXX ? trk[bC * TILE + tid] : (bC * TILE + tid) % n;
        }
    }
    asm volatile("cp.async.commit_group;" ::: "memory");

    for (; t < totTiles; t += gridDim.x) {
        bool offDiag = isXX && (bR < bC);
        bool hasDiag = isXX && (bR == bC);
        int grow0 = bR * TILE;
        int gcol0 = bC * TILE;

        asm volatile("cp.async.wait_group 0;" ::: "memory");
        __syncthreads();

        // ---- MMA ----
        float acc[4][4][4];
#pragma unroll
        for (int mi = 0; mi < 4; mi++)
#pragma unroll
            for (int ni = 0; ni < 4; ni++)
#pragma unroll
                for (int e = 0; e < 4; e++) acc[mi][ni][e] = 0.f;

#pragma unroll
        for (int ks = 0; ks < 8; ks++) {
            uint32_t a[4][4], b[2][4];
#pragma unroll
            for (int mi = 0; mi < 4; mi++) ldmx4(a[mi], aAddr[mi] + ks * 32);
#pragma unroll
            for (int g = 0; g < 2; g++) ldmx4(b[g], bAddr[g] + ks * 32);
#pragma unroll
            for (int mi = 0; mi < 4; mi++) {
                mma16816(acc[mi][0], a[mi], b[0][0], b[0][2]);
                mma16816(acc[mi][1], a[mi], b[0][1], b[0][3]);
                mma16816(acc[mi][2], a[mi], b[1][0], b[1][2]);
                mma16816(acc[mi][3], a[mi], b[1][1], b[1][3]);
            }
        }
        __syncthreads();   // all warps done reading A/B smem

        // ---- prefetch next tile into the (now dead) A/B buffers ----
        int nt = t + gridDim.x;
        int nbR = 0, nbC = 0; bool nisXX = true;
        if (nt < totTiles) {
            tile_coords(nt, nXX, tri, nXYc, nbR, nbC, nisXX);
            const __nv_bfloat16* asrc = g_xs + (size_t)nbR * TILE * DK;
            const __nv_bfloat16* bsrc = nisXX ? (g_xb + (size_t)nbC * TILE * DK)
                                              : (g_yb + (size_t)nbC * TILE * DK);
#pragma unroll
            for (int it = 0; it < 8; it++) {
                int c = tid + it * 256;
                int row = c >> 4;
                int col8 = (c & 15) << 3;
                cpasync16(sb + SM_A + (row * ASTR + col8) * 2, asrc + (size_t)row * DK + col8);
                cpasync16(sb + SM_B + (row * ASTR + col8) * 2, bsrc + (size_t)row * DK + col8);
            }
            int nx = cur ^ 1;
            if (tid < 128) {
                trS[nx * 128 + tid] = trk[nbR * TILE + tid];
                tcS[nx * 128 + tid] = nisXX ? trk[nbC * TILE + tid]
                                            : (nbC * TILE + tid) % n;
            }
        }
        asm volatile("cp.async.commit_group;" ::: "memory");

        // ---- epilogue (overlaps with in-flight cp.async) ----
        const int* trC = trS + cur * 128;
        const int* tcC = tcS + cur * 128;
        int tcJ[8];
#pragma unroll
        for (int j = 0; j < 8; j++) {
            int ni = j >> 1, p = j & 1;
            tcJ[j] = tcC[n0 + ni * 8 + t4 * 2 + p];
        }

        float cs[4][2] = {{0.f, 0.f}, {0.f, 0.f}, {0.f, 0.f}, {0.f, 0.f}};
#pragma unroll
        for (int mi = 0; mi < 4; mi++) {
#pragma unroll
            for (int h = 0; h < 2; h++) {
                int rloc = m0 + mi * 16 + q + h * 8;
                int tr = trC[rloc];
                int grow = grow0 + rloc;
                float r_s = 0.f, s_s = 0.f;
#pragma unroll
                for (int ni = 0; ni < 4; ni++) {
#pragma unroll
                    for (int p = 0; p < 2; p++) {
                        float e = ex2f(acc[mi][ni][h * 2 + p]);   // A prescaled
                        r_s += e;
                        if (tcJ[ni * 2 + p] == tr) s_s += e;
                        if (hasDiag && (gcol0 + n0 + ni * 8 + t4 * 2 + p == grow))
                            atomicAdd(&g_DS[tr], (double)e);
                        if (offDiag) cs[ni][p] += e;
                    }
                }
                r_s += __shfl_xor_sync(0xffffffffu, r_s, 1);
                r_s += __shfl_xor_sync(0xffffffffu, r_s, 2);
                s_s += __shfl_xor_sync(0xffffffffu, s_s, 1);
                s_s += __shfl_xor_sync(0xffffffffu, s_s, 2);
                if (t4 == 0) {
                    atomicAdd(&rowRS[rloc], r_s);
                    atomicAdd(&rowSS[rloc], s_s);
                }
            }
        }

        if (offDiag) {
#pragma unroll
            for (int ni = 0; ni < 4; ni++) {
#pragma unroll
                for (int p = 0; p < 2; p++) {
                    float v = cs[ni][p];
                    v += __shfl_xor_sync(0xffffffffu, v, 4);
                    v += __shfl_xor_sync(0xffffffffu, v, 8);
                    v += __shfl_xor_sync(0xffffffffu, v, 16);
                    if (q == 0)
                        atomicAdd(&colCS[n0 + ni * 8 + t4 * 2 + p], v);
                }
            }
        }
        __syncthreads();

        if (tid < 128) {
            int tr = trC[tid];
            if (isXX) {
                atomicAdd(&g_RT[tr], (double)rowRS[tid]);
                atomicAdd(&g_G[tr], (double)((offDiag ? 2.0f : 1.0f) * rowSS[tid]));
                if (offDiag)
                    atomicAdd(&g_RT[tcC[tid]], (double)colCS[tid]);
            } else {
                atomicAdd(&g_A[tr], (double)rowRS[tid]);
                atomicAdd(&g_P[tr], (double)rowSS[tid]);
            }
            rowRS[tid] = 0.f; rowSS[tid] = 0.f; colCS[tid] = 0.f;
        }

        bR = nbR; bC = nbC; isXX = nisXX;
        cur ^= 1;
    }
}

// ---------------------------------------------------------------------------
__global__ void k_loss(float* out, int nQ) {
    __shared__ double warpsum[16];
    int n = g_n;
    int Q = nQ / n;
    double local = 0.0;
    for (int i = threadIdx.x; i < n; i += blockDim.x) {
        double num = g_P[i] + 0.5 * (g_G[i] - g_DS[i]);
        double den = (g_A[i] - g_P[i]) + (g_RT[i] - g_G[i]);
        local += (double)logf((float)((num + den) / num));
    }
#pragma unroll
    for (int o = 16; o >= 1; o >>= 1)
        local += __shfl_xor_sync(0xffffffffu, local, o);
    int lane = threadIdx.x & 31, wi = threadIdx.x >> 5;
    if (lane == 0) warpsum[wi] = local;
    __syncthreads();
    if (threadIdx.x == 0) {
        double t = 0.0;
        for (int i = 0; i < (int)(blockDim.x >> 5); i++) t += warpsum[i];
        out[0] = (float)(t / (double)n / (double)Q);
    }
}

// ---------------------------------------------------------------------------
extern "C" void kernel_launch(void* const* d_in, const int* in_sizes, int n_in,
                              void* d_out, int out_size) {
    const float* x   = (const float*)d_in[0];
    const int*   trk = (const int*)d_in[1];
    const float* y   = (const float*)d_in[2];
    float* out = (float*)d_out;

    int M  = in_sizes[1];
    int D  = in_sizes[0] / M;
    int nQ = in_sizes[2] / D;

    cudaFuncSetAttribute(k_gemm, cudaFuncAttributeMaxDynamicSharedMemorySize, SM_TOTAL);

    int prepThreads = (M * D + nQ * D) / 4;
    if (prepThreads < MAX_M) prepThreads = MAX_M;
    k_prep<<<(prepThreads + 255) / 256, 256>>>(x, y, trk, M, nQ);

    k_gemm<<<NPCTA, 256, SM_TOTAL>>>(trk, M, nQ);

    k_loss<<<1, 512>>>(out, nQ);
}